// round 5
// baseline (speedup 1.0000x reference)
#include <cuda_runtime.h>
#include <cstdint>

#define FULLMASK 0xFFFFFFFFu

typedef unsigned long long u64;

static constexpr int NB      = 131072;
static constexpr int NO      = 128;
static constexpr int NF      = 32;
static constexpr int WPB     = 8;           // warps per block
static constexpr int THREADS = WPB * 32;    // 256
static constexpr int NBLOCKS = 2048;
static constexpr int TOTAL_WARPS = NBLOCKS * WPB;   // 16384
static constexpr int ITERS   = NB / TOTAL_WARPS;    // 8 samples per warp

// ---- f32x2 packed helpers (Blackwell sm_100a). Carrier type is u64 because
// the "l" asm constraint binds 64-bit integer registers. -----------------------
__device__ __forceinline__ u64 pack2(float lo, float hi) {
    u64 r;
    asm("mov.b64 %0, {%1,%2};" : "=l"(r) : "f"(lo), "f"(hi));
    return r;
}
__device__ __forceinline__ void unpack2(u64 a, float& lo, float& hi) {
    asm("mov.b64 {%0,%1}, %2;" : "=f"(lo), "=f"(hi) : "l"(a));
}
// r = a*b + c   elementwise on packed f32x2
__device__ __forceinline__ u64 ffma2(u64 a, u64 b, u64 c) {
    u64 r;
    asm("fma.rn.f32x2 %0, %1, %2, %3;" : "=l"(r) : "l"(a), "l"(b), "l"(c));
    return r;
}

__global__ __launch_bounds__(THREADS, 3)
void slater_det_kernel(const int4* __restrict__ nvec,
                       const float* __restrict__ Phi,
                       float* __restrict__ out)
{
    // PhiT[o*32 + i] = Phi[i*128 + o]  (stride-32 => conflict-free lane gather)
    __shared__ float      PhiT[NO * NF];
    __shared__ int        idxs[WPB][NF];
    __shared__ ulonglong2 prow[WPB][2][8];   // double-buffered pivot-row broadcast
    __shared__ ulonglong2 dump[8];           // write sink for non-pivot lanes (branch-free STS)

    const int tid = threadIdx.x;
    for (int l = tid; l < NO * NF; l += THREADS) {
        const int o = l >> 5;       // orbital
        const int i = l & 31;       // row of Phi
        PhiT[l] = Phi[i * NO + o];  // STS conflict-free; GMEM reads hit L2 (Phi is 16KB)
    }
    __syncthreads();

    const int wid  = tid >> 5;
    const int lane = tid & 31;
    int* mi = idxs[wid];
    const int gw = blockIdx.x * WPB + wid;

    for (int it = 0; it < ITERS; ++it) {
        const int s = gw + it * TOTAL_WARPS;

        // ---- occupied-orbital extraction (ascending order) -------------------
        const int4 v = nvec[s * (NO / 4) + lane];          // coalesced 512B/warp
        const int c0 = (v.x != 0) + (v.y != 0) + (v.z != 0) + (v.w != 0);
        int pref = c0;
        #pragma unroll
        for (int d = 1; d < 32; d <<= 1) {
            const int t = __shfl_up_sync(FULLMASK, pref, d);
            if (lane >= d) pref += t;
        }
        int pos = pref - c0;                                // exclusive prefix
        __syncwarp();                                       // protect mi / prow reuse
        if (v.x) mi[pos++] = 4 * lane + 0;
        if (v.y) mi[pos++] = 4 * lane + 1;
        if (v.z) mi[pos++] = 4 * lane + 2;
        if (v.w) mi[pos++] = 4 * lane + 3;
        __syncwarp();

        // ---- gather: lane = row, A[q] packs columns (2q, 2q+1) ---------------
        u64 A[16];
        #pragma unroll
        for (int q = 0; q < 16; ++q) {
            const int o0 = mi[2 * q + 0];
            const int o1 = mi[2 * q + 1];
            A[q] = pack2(PhiT[o0 * 32 + lane], PhiT[o1 * 32 + lane]);
        }

        // ---- LU with partial pivoting (virtual row permutation) --------------
        float det  = 1.0f;
        int  myrow = lane;
        #pragma unroll
        for (int k = 0; k < 32; ++k) {
            float lo, hi;
            unpack2(A[k >> 1], lo, hi);
            const float ak = (k & 1) ? hi : lo;             // this lane's col-k value

            const bool active = (myrow >= k);
            const unsigned key = active ? __float_as_uint(fabsf(ak)) : 0u;
            const unsigned mx  = __reduce_max_sync(FULLMASK, key);
            const unsigned cand = __ballot_sync(FULLMASK, active && (key == mx));
            const int p = __ffs(cand) - 1;                  // pivot lane
            const int r = __shfl_sync(FULLMASK, myrow, p);  // pivot virtual row

            const unsigned hb = __ballot_sync(FULLMASK, myrow == k);
            const int h = __ffs(hb) - 1;                    // holder of virtual row k
            if (lane == h) myrow = r;                       // swap bookkeeping
            if (lane == p) myrow = k;

            const float pv = __shfl_sync(FULLMASK, ak, p);
            det *= (r != k) ? -pv : pv;                     // sign folded in

            float inv;
            asm("rcp.approx.f32 %0, %1;" : "=f"(inv) : "f"(pv));
            inv = (pv != 0.f) ? inv : 0.f;                  // singular guard -> det 0
            const float f = (myrow > k) ? ak * inv : 0.f;   // pivot/eliminated rows: f=0
            const u64 nf2 = pack2(-f, -f);

            if (k < 31) {
                const int q4 = (k >> 1) & ~1;               // even pair start (cols >= 4*(k/4))
                // branch-free pivot-row broadcast: non-pivot lanes write to dump
                ulonglong2* dst = (lane == p) ? &prow[wid][k & 1][0] : &dump[0];
                #pragma unroll
                for (int q = q4; q < 16; q += 2)
                    dst[q >> 1] = make_ulonglong2(A[q], A[q + 1]);
                __syncwarp();
                const ulonglong2* src = &prow[wid][k & 1][0];
                #pragma unroll
                for (int q = q4; q < 16; q += 2) {
                    const ulonglong2 b = src[q >> 1];
                    A[q]     = ffma2(b.x, nf2, A[q]);       // spurious cols <= k are ~0: harmless
                    A[q + 1] = ffma2(b.y, nf2, A[q + 1]);
                }
            }
        }

        if (lane == 0) out[s] = det;
    }
}

extern "C" void kernel_launch(void* const* d_in, const int* in_sizes, int n_in,
                              void* d_out, int out_size)
{
    const int4*  nvec = (const int4*)d_in[0];   // n: [131072, 128] int32
    const float* Phi  = (const float*)d_in[1];  // Phi: [32, 128] fp32
    float* out = (float*)d_out;                 // [131072] fp32
    slater_det_kernel<<<NBLOCKS, THREADS>>>(nvec, Phi, out);
}

// round 6
// speedup vs baseline: 1.4566x; 1.4566x over previous
#include <cuda_runtime.h>
#include <cstdint>

#define FULLMASK 0xFFFFFFFFu
typedef unsigned long long u64;

static constexpr int NB      = 131072;
static constexpr int NO      = 128;
static constexpr int NF      = 32;
static constexpr int WPB     = 8;
static constexpr int THREADS = WPB * 32;            // 256
static constexpr int NBLOCKS = 2048;
static constexpr int TOTAL_WARPS = NBLOCKS * WPB;   // 16384
static constexpr int ITERS   = NB / (TOTAL_WARPS * 2);  // 4 (2 samples/warp/iter)

// ---- f32x2 packed helpers; carrier is u64 ("l" binds 64-bit int regs) --------
__device__ __forceinline__ u64 pack2(float lo, float hi) {
    u64 r;
    asm("mov.b64 %0, {%1,%2};" : "=l"(r) : "f"(lo), "f"(hi));
    return r;
}
__device__ __forceinline__ void unpack2(u64 a, float& lo, float& hi) {
    asm("mov.b64 {%0,%1}, %2;" : "=f"(lo), "=f"(hi) : "l"(a));
}
__device__ __forceinline__ u64 ffma2(u64 a, u64 b, u64 c) {
    u64 r;
    asm("fma.rn.f32x2 %0, %1, %2, %3;" : "=l"(r) : "l"(a), "l"(b), "l"(c));
    return r;
}

__global__ __launch_bounds__(THREADS, 2)
void slater_det_kernel(const int4* __restrict__ nvec,
                       const float* __restrict__ Phi,
                       float* __restrict__ out)
{
    // PhiT[o*33 + i] = Phi[i*128 + o]; stride 33 decorrelates the two
    // half-warps' gather banks (i = t vs t+16).
    __shared__ float PhiT[NO * 33];
    __shared__ int   idxs[WPB][2][NF];

    const int tid = threadIdx.x;
    for (int l = tid; l < NO * NF; l += THREADS) {
        const int o = l >> 5;
        const int i = l & 31;
        PhiT[o * 33 + i] = Phi[i * NO + o];
    }
    __syncthreads();

    const int wid  = tid >> 5;
    const int lane = tid & 31;
    const int h    = lane >> 4;     // half-warp = which of 2 samples
    const int t    = lane & 15;     // sublane; this lane owns rows t and t+16
    int* mi = idxs[wid][h];
    const int gw = blockIdx.x * WPB + wid;

    for (int it = 0; it < ITERS; ++it) {
        const int s = 2 * (gw + it * TOTAL_WARPS) + h;

        // ---- occupied-orbital extraction (ascending), per half-warp ---------
        const int4 va = nvec[s * 32 + 2 * t + 0];
        const int4 vb = nvec[s * 32 + 2 * t + 1];
        const int c = (va.x != 0) + (va.y != 0) + (va.z != 0) + (va.w != 0)
                    + (vb.x != 0) + (vb.y != 0) + (vb.z != 0) + (vb.w != 0);
        int pref = c;
        #pragma unroll
        for (int d = 1; d < 16; d <<= 1) {
            const int u = __shfl_up_sync(FULLMASK, pref, d);
            if (t >= d) pref += u;
        }
        int pos = pref - c;                 // exclusive prefix within half
        __syncwarp();                       // prior gather reads done before rewrite
        const int base = 8 * t;
        if (va.x) mi[pos++] = base + 0;
        if (va.y) mi[pos++] = base + 1;
        if (va.z) mi[pos++] = base + 2;
        if (va.w) mi[pos++] = base + 3;
        if (vb.x) mi[pos++] = base + 4;
        if (vb.y) mi[pos++] = base + 5;
        if (vb.z) mi[pos++] = base + 6;
        if (vb.w) mi[pos++] = base + 7;
        __syncwarp();

        // ---- gather: A0 = row t, A1 = row t+16; cols packed in pairs --------
        u64 A0[16], A1[16];
        #pragma unroll
        for (int q = 0; q < 16; ++q) {
            const int o0 = mi[2 * q + 0];
            const int o1 = mi[2 * q + 1];
            A0[q] = pack2(PhiT[o0 * 33 + t],      PhiT[o1 * 33 + t]);
            A1[q] = pack2(PhiT[o0 * 33 + t + 16], PhiT[o1 * 33 + t + 16]);
        }

        // ---- LU with partial pivoting, virtual rows, shfl broadcast ---------
        float det = 1.0f;
        int vr0 = t, vr1 = t + 16;
        #pragma unroll
        for (int k = 0; k < 32; ++k) {
            float l0, h0, l1, h1;
            unpack2(A0[k >> 1], l0, h0);
            unpack2(A1[k >> 1], l1, h1);
            const float ak0 = (k & 1) ? h0 : l0;
            const float ak1 = (k & 1) ? h1 : l1;

            // per-lane best of its 2 rows (eligible = vr >= k)
            const unsigned key0 = (vr0 >= k) ? __float_as_uint(fabsf(ak0)) : 0u;
            const unsigned key1 = (vr1 >= k) ? __float_as_uint(fabsf(ak1)) : 0u;
            const bool sl = key1 > key0;
            // packed argmax: low 5 bits carry lane (31-ulp tie fuzz is harmless)
            unsigned pk = ((sl ? key1 : key0) & 0xFFFFFFE0u) | (unsigned)lane;
            #pragma unroll
            for (int d = 1; d < 16; d <<= 1)
                pk = max(pk, __shfl_xor_sync(FULLMASK, pk, d));
            const int p = (int)(pk & 31u);          // pivot lane (per half)

            const float pcand = sl ? ak1 : ak0;
            const float pv = __shfl_sync(FULLMASK, pcand, p);
            int rsel = ((sl ? vr1 : vr0) << 1) | (int)sl;
            rsel = __shfl_sync(FULLMASK, rsel, p);
            const int  r    = rsel >> 1;            // pivot's virtual row
            const bool psel = rsel & 1;             // pivot used its row1?

            // virtual swap (old vrs): holder of row k takes r; pivot takes k
            const bool h0k = (vr0 == k), h1k = (vr1 == k);
            if (h0k) vr0 = r; else if (h1k) vr1 = r;
            if (lane == p) { if (psel) vr1 = k; else vr0 = k; }

            det *= (r != k) ? -pv : pv;

            float inv;
            asm("rcp.approx.f32 %0, %1;" : "=f"(inv) : "f"(pv));
            inv = (pv != 0.f) ? inv : 0.f;          // singular -> det 0
            const float f0 = (vr0 > k) ? ak0 * inv : 0.f;
            const float f1 = (vr1 > k) ? ak1 * inv : 0.f;
            const u64 nf0 = pack2(-f0, -f0);
            const u64 nf1 = pack2(-f1, -f1);

            if (k < 31) {
                const int q4 = (k >> 1) & ~1;       // first pair = 2*floor(k/4)
                #pragma unroll
                for (int q = q4; q < 16; ++q) {
                    const u64 tq = psel ? A1[q] : A0[q];
                    const u64 b  = __shfl_sync(FULLMASK, tq, p);  // 2x SHFL.32
                    A0[q] = ffma2(b, nf0, A0[q]);
                    A1[q] = ffma2(b, nf1, A1[q]);
                }
            }
        }

        if (t == 0) out[s] = det;
    }
}

extern "C" void kernel_launch(void* const* d_in, const int* in_sizes, int n_in,
                              void* d_out, int out_size)
{
    const int4*  nvec = (const int4*)d_in[0];   // n: [131072, 128] int32
    const float* Phi  = (const float*)d_in[1];  // Phi: [32, 128] fp32
    float* out = (float*)d_out;                 // [131072] fp32
    slater_det_kernel<<<NBLOCKS, THREADS>>>(nvec, Phi, out);
}

// round 7
// speedup vs baseline: 1.5226x; 1.0453x over previous
#include <cuda_runtime.h>
#include <cstdint>

#define FULLMASK 0xFFFFFFFFu
typedef unsigned long long u64;

static constexpr int NB      = 131072;
static constexpr int NO      = 128;
static constexpr int NF      = 32;
static constexpr int WPB     = 4;
static constexpr int THREADS = WPB * 32;            // 128
static constexpr int NBLOCKS = 4096;
static constexpr int TOTAL_WARPS = NBLOCKS * WPB;   // 16384
static constexpr int ITERS   = NB / (TOTAL_WARPS * 2);  // 4 (2 samples/warp/iter)

// ---- f32x2 packed helpers; carrier is u64 ("l" binds 64-bit int regs) --------
__device__ __forceinline__ u64 pack2(float lo, float hi) {
    u64 r;
    asm("mov.b64 %0, {%1,%2};" : "=l"(r) : "f"(lo), "f"(hi));
    return r;
}
__device__ __forceinline__ void unpack2(u64 a, float& lo, float& hi) {
    asm("mov.b64 {%0,%1}, %2;" : "=f"(lo), "=f"(hi) : "l"(a));
}
__device__ __forceinline__ u64 ffma2(u64 a, u64 b, u64 c) {
    u64 r;
    asm("fma.rn.f32x2 %0, %1, %2, %3;" : "=l"(r) : "l"(a), "l"(b), "l"(c));
    return r;
}

__global__ __launch_bounds__(THREADS, 5)   // cap regs ~102 -> 5 blocks = 20 warps/SM
void slater_det_kernel(const int4* __restrict__ nvec,
                       const float* __restrict__ Phi,
                       float* __restrict__ out)
{
    // PhiT[o*33 + i] = Phi[i*128 + o]; stride 33 decorrelates half-warp banks.
    __shared__ float PhiT[NO * 33];
    __shared__ int   idxs[WPB][2][NF];

    const int tid = threadIdx.x;
    for (int l = tid; l < NO * NF; l += THREADS) {
        const int o = l >> 5;
        const int i = l & 31;
        PhiT[o * 33 + i] = Phi[i * NO + o];
    }
    __syncthreads();

    const int wid  = tid >> 5;
    const int lane = tid & 31;
    const int h    = lane >> 4;     // half-warp = which of 2 samples
    const int t    = lane & 15;     // sublane; owns rows t and t+16
    int* mi = idxs[wid][h];
    const int gw = blockIdx.x * WPB + wid;

    for (int it = 0; it < ITERS; ++it) {
        const int s = 2 * (gw + it * TOTAL_WARPS) + h;

        // ---- occupied-orbital extraction (ascending), per half-warp ---------
        const int4 va = nvec[s * 32 + 2 * t + 0];
        const int4 vb = nvec[s * 32 + 2 * t + 1];
        const int c = (va.x != 0) + (va.y != 0) + (va.z != 0) + (va.w != 0)
                    + (vb.x != 0) + (vb.y != 0) + (vb.z != 0) + (vb.w != 0);
        int pref = c;
        #pragma unroll
        for (int d = 1; d < 16; d <<= 1) {
            const int u = __shfl_up_sync(FULLMASK, pref, d);
            if (t >= d) pref += u;
        }
        int pos = pref - c;                 // exclusive prefix within half
        __syncwarp();
        const int base = 8 * t;
        if (va.x) mi[pos++] = base + 0;
        if (va.y) mi[pos++] = base + 1;
        if (va.z) mi[pos++] = base + 2;
        if (va.w) mi[pos++] = base + 3;
        if (vb.x) mi[pos++] = base + 4;
        if (vb.y) mi[pos++] = base + 5;
        if (vb.z) mi[pos++] = base + 6;
        if (vb.w) mi[pos++] = base + 7;
        __syncwarp();

        // ---- gather: A0 = row t, A1 = row t+16; cols packed in pairs --------
        u64 A0[16], A1[16];
        #pragma unroll
        for (int q = 0; q < 16; ++q) {
            const int o0 = mi[2 * q + 0];
            const int o1 = mi[2 * q + 1];
            A0[q] = pack2(PhiT[o0 * 33 + t],      PhiT[o1 * 33 + t]);
            A1[q] = pack2(PhiT[o0 * 33 + t + 16], PhiT[o1 * 33 + t + 16]);
        }

        // ---- LU with partial pivoting, virtual rows, shfl broadcast ---------
        float det = 1.0f;
        int vr0 = t, vr1 = t + 16;
        unsigned m0 = ~0u, m1 = ~0u;        // life masks: ~0 while row active
        #pragma unroll
        for (int k = 0; k < 32; ++k) {
            float l0, h0, l1, h1;
            unpack2(A0[k >> 1], l0, h0);
            unpack2(A1[k >> 1], l1, h1);
            const float ak0 = (k & 1) ? h0 : l0;
            const float ak1 = (k & 1) ? h1 : l1;

            // keys: |ak| & life-mask, one LOP3 each
            const unsigned key0 = __float_as_uint(ak0) & 0x7FFFFFFFu & m0;
            const unsigned key1 = __float_as_uint(ak1) & 0x7FFFFFFFu & m1;
            const bool sl = key1 > key0;
            // packed argmax within half: low 5 bits carry lane (tie fuzz harmless)
            unsigned pk = ((sl ? key1 : key0) & 0xFFFFFFE0u) | (unsigned)lane;
            #pragma unroll
            for (int d = 1; d < 16; d <<= 1)
                pk = max(pk, __shfl_xor_sync(FULLMASK, pk, d));
            const int p = (int)(pk & 31u);          // pivot lane (per half)

            const float pcand = sl ? ak1 : ak0;
            const float pv = __shfl_sync(FULLMASK, pcand, p);
            int rsel = ((sl ? vr1 : vr0) << 1) | (int)sl;
            rsel = __shfl_sync(FULLMASK, rsel, p);
            const int  r    = rsel >> 1;            // pivot's virtual row
            const bool psel = rsel & 1;             // pivot used its row1?

            // virtual swap: holder of row k takes r; pivot takes k (and dies)
            if (vr0 == k) vr0 = r; else if (vr1 == k) vr1 = r;
            if (lane == p) {
                if (psel) { vr1 = k; m1 = 0u; }
                else      { vr0 = k; m0 = 0u; }
            }

            det *= (r != k) ? -pv : pv;

            float inv;
            asm("rcp.approx.f32 %0, %1;" : "=f"(inv) : "f"(pv));
            inv = (pv != 0.f) ? inv : 0.f;          // singular -> det 0
            // -f = (bits(ak*inv) & mask) ^ signbit : single LOP3 each
            const float nf0f = __uint_as_float((__float_as_uint(ak0 * inv) & m0) ^ 0x80000000u);
            const float nf1f = __uint_as_float((__float_as_uint(ak1 * inv) & m1) ^ 0x80000000u);
            const u64 nf0 = pack2(nf0f, nf0f);
            const u64 nf1 = pack2(nf1f, nf1f);

            if (k < 31) {
                const int q4 = k >> 1;              // exact trim (no alignment need)
                #pragma unroll
                for (int q = q4; q < 16; ++q) {
                    const u64 tq = psel ? A1[q] : A0[q];
                    const u64 b  = __shfl_sync(FULLMASK, tq, p);  // 2x SHFL.32
                    A0[q] = ffma2(b, nf0, A0[q]);
                    A1[q] = ffma2(b, nf1, A1[q]);
                }
            }
        }

        if (t == 0) out[s] = det;
    }
}

extern "C" void kernel_launch(void* const* d_in, const int* in_sizes, int n_in,
                              void* d_out, int out_size)
{
    const int4*  nvec = (const int4*)d_in[0];   // n: [131072, 128] int32
    const float* Phi  = (const float*)d_in[1];  // Phi: [32, 128] fp32
    float* out = (float*)d_out;                 // [131072] fp32
    slater_det_kernel<<<NBLOCKS, THREADS>>>(nvec, Phi, out);
}